// round 1
// baseline (speedup 1.0000x reference)
#include <cuda_runtime.h>
#include <math.h>

#define DIM_E   256
#define NH1     32
#define NH2     16
#define MAX_D   1024
#define OPK_T   256
#define MAX_BLK 1024

// ---------------- device scratch (no allocations allowed) ----------------
__device__ float g_zsum_op[NH1];
__device__ float g_zsum_pr[NH1];
__device__ float g_ydag_op[MAX_D * NH1];
__device__ float g_ydag_pr[MAX_D * NH1];
__device__ int   g_off[MAX_D + 1];
__device__ float g_bsum[MAX_BLK];
__device__ float g_total;

// ---------------- f32x2 packed-FMA helpers (FFMA2) ----------------
__device__ __forceinline__ unsigned long long pack2(float lo, float hi) {
    unsigned long long r;
    asm("mov.b64 %0, {%1, %2};" : "=l"(r) : "f"(lo), "f"(hi));
    return r;
}
__device__ __forceinline__ void fma2(unsigned long long& d, unsigned long long a,
                                     unsigned long long b) {
    asm("fma.rn.f32x2 %0, %1, %2, %0;" : "+l"(d) : "l"(a), "l"(b));
}
__device__ __forceinline__ float2 unpack2(unsigned long long v) {
    float2 f;
    asm("mov.b64 {%0, %1}, %2;" : "=f"(f.x), "=f"(f.y) : "l"(v));
    return f;
}

// ---------------- kernel 1: exclusive scan of num_ops -> g_off ----------------
__global__ void scan_kernel(const int* __restrict__ num_ops, int D) {
    __shared__ int s[1024];
    int t = threadIdx.x;
    int v = (t < D) ? num_ops[t] : 0;
    s[t] = v;
    __syncthreads();
    for (int off = 1; off < 1024; off <<= 1) {
        int add = (t >= off) ? s[t - off] : 0;
        __syncthreads();
        s[t] += add;
        __syncthreads();
    }
    if (t < D) g_off[t + 1] = s[t];
    if (t == 0) g_off[0] = 0;
}

// ---------------- kernel 2: z contributions (z@W1z + b1) ----------------
__global__ void zsum_kernel(const float* __restrict__ z,
                            const float* __restrict__ opW1, const float* __restrict__ opb1,
                            const float* __restrict__ prW1, const float* __restrict__ prb1) {
    int t = threadIdx.x;
    if (t < NH1) {
        float a = opb1[t];
        for (int k = 0; k < DIM_E; k++)
            a += z[k] * opW1[(2 * DIM_E + k) * NH1 + t];
        g_zsum_op[t] = a;
    } else if (t < 2 * NH1) {
        int j = t - NH1;
        float a = prb1[j];
        for (int k = 0; k < DIM_E; k++)
            a += z[k] * prW1[(1 + DIM_E + k) * NH1 + j];
        g_zsum_pr[j] = a;
    }
}

// ---------------- kernel 3: per-dag y contributions ----------------
__global__ void ydag_kernel(const float* __restrict__ y,
                            const float* __restrict__ opW1,
                            const float* __restrict__ prW1) {
    int d = blockIdx.x;
    int t = threadIdx.x;
    __shared__ float sy[DIM_E];
    for (int k = t; k < DIM_E; k += 64) sy[k] = y[d * DIM_E + k];
    __syncthreads();
    if (t < NH1) {
        float a = 0.f;
        #pragma unroll 8
        for (int k = 0; k < DIM_E; k++)
            a += sy[k] * opW1[(DIM_E + k) * NH1 + t];
        g_ydag_op[d * NH1 + t] = a;
    } else {
        int j = t - NH1;
        float a = 0.f;
        #pragma unroll 8
        for (int k = 0; k < DIM_E; k++)
            a += sy[k] * prW1[(1 + k) * NH1 + j];
        g_ydag_pr[d * NH1 + j] = a;
    }
}

// ---------------- kernel 4: op branch main (logits -> exp, block sums) ----------------
__global__ __launch_bounds__(OPK_T) void op_main(
    const float* __restrict__ x,
    const float* __restrict__ opW1,
    const float* __restrict__ opW2, const float* __restrict__ opb2,
    const float* __restrict__ opW3, const float* __restrict__ opb3,
    const float* __restrict__ op_msk,
    float* __restrict__ out, int N, int D)
{
    __shared__ float4 sW1f[DIM_E * NH1 / 4];           // 32 KB: W1 x-part
    __shared__ unsigned long long sW2u[NH1 * NH2 / 2]; // 2 KB : W2 as pairs
    __shared__ float sW3[NH2];
    __shared__ float sB2[NH2];
    __shared__ float sInit[NH1];                       // z part + b1
    __shared__ int   sOff[MAX_D + 1];
    __shared__ float swarp[OPK_T / 32];

    int t = threadIdx.x;

    const float4* gw = (const float4*)opW1;            // rows 0..255 = x part
    for (int i = t; i < DIM_E * NH1 / 4; i += OPK_T) sW1f[i] = gw[i];
    {
        const float2* gw2 = (const float2*)opW2;
        float2* sw2 = (float2*)sW2u;
        for (int i = t; i < NH1 * NH2 / 2; i += OPK_T) sw2[i] = gw2[i];
    }
    if (t < NH2) { sW3[t] = opW3[t]; sB2[t] = opb2[t]; }
    if (t < NH1) sInit[t] = g_zsum_op[t];
    for (int i = t; i <= D; i += OPK_T) sOff[i] = g_off[i];
    __syncthreads();

    int n  = blockIdx.x * OPK_T + t;
    int nc = n < N ? n : N - 1;

    // dag id via binary search on offsets
    int lo = 0, hi = D;
    while (hi - lo > 1) {
        int mid = (lo + hi) >> 1;
        if (nc >= sOff[mid]) lo = mid; else hi = mid;
    }
    int dag = lo;

    // layer 1: 16 packed f32x2 accumulators
    unsigned long long acc[NH1 / 2];
    {
        const float2* yi = (const float2*)(g_ydag_op + dag * NH1);
        const float2* zi = (const float2*)sInit;
        #pragma unroll
        for (int j = 0; j < NH1 / 2; j++) {
            float2 a = yi[j], b = zi[j];
            acc[j] = pack2(a.x + b.x, a.y + b.y);
        }
    }
    const float4* xrow = (const float4*)(x + (size_t)nc * DIM_E);
    const unsigned long long* sW1 = (const unsigned long long*)sW1f;
    #pragma unroll 2
    for (int k4 = 0; k4 < DIM_E / 4; k4++) {
        float4 xv = __ldg(&xrow[k4]);
        unsigned long long xx0 = pack2(xv.x, xv.x);
        unsigned long long xx1 = pack2(xv.y, xv.y);
        unsigned long long xx2 = pack2(xv.z, xv.z);
        unsigned long long xx3 = pack2(xv.w, xv.w);
        const unsigned long long* w = &sW1[k4 * 4 * (NH1 / 2)];
        #pragma unroll
        for (int j = 0; j < NH1 / 2; j++) fma2(acc[j], xx0, w[0 * (NH1/2) + j]);
        #pragma unroll
        for (int j = 0; j < NH1 / 2; j++) fma2(acc[j], xx1, w[1 * (NH1/2) + j]);
        #pragma unroll
        for (int j = 0; j < NH1 / 2; j++) fma2(acc[j], xx2, w[2 * (NH1/2) + j]);
        #pragma unroll
        for (int j = 0; j < NH1 / 2; j++) fma2(acc[j], xx3, w[3 * (NH1/2) + j]);
    }

    // relu -> h1
    float h1[NH1];
    #pragma unroll
    for (int j = 0; j < NH1 / 2; j++) {
        float2 f = unpack2(acc[j]);
        h1[2 * j]     = fmaxf(f.x, 0.f);
        h1[2 * j + 1] = fmaxf(f.y, 0.f);
    }

    // layer 2 (packed)
    unsigned long long a2[NH2 / 2];
    {
        const float2* b2p = (const float2*)sB2;
        #pragma unroll
        for (int j = 0; j < NH2 / 2; j++) { float2 b = b2p[j]; a2[j] = pack2(b.x, b.y); }
    }
    #pragma unroll
    for (int k = 0; k < NH1; k++) {
        unsigned long long hk = pack2(h1[k], h1[k]);
        #pragma unroll
        for (int j = 0; j < NH2 / 2; j++) fma2(a2[j], hk, sW2u[k * (NH2 / 2) + j]);
    }

    // layer 3
    float o = opb3[0];
    #pragma unroll
    for (int j = 0; j < NH2 / 2; j++) {
        float2 f = unpack2(a2[j]);
        o += fmaxf(f.x, 0.f) * sW3[2 * j] + fmaxf(f.y, 0.f) * sW3[2 * j + 1];
    }

    float e = 0.f;
    if (n < N) {
        float logit = o - (1.0f - op_msk[n]) * 1000.0f;
        e = expf(logit);          // masked -> expf(~-1000) == 0.0f exactly
        out[n] = e;
    }

    // deterministic block sum
    float v = e;
    #pragma unroll
    for (int off = 16; off > 0; off >>= 1) v += __shfl_down_sync(0xffffffffu, v, off);
    if ((t & 31) == 0) swarp[t >> 5] = v;
    __syncthreads();
    if (t == 0) {
        float a = 0.f;
        #pragma unroll
        for (int i = 0; i < OPK_T / 32; i++) a += swarp[i];
        g_bsum[blockIdx.x] = a;
    }
}

// ---------------- kernel 5: reduce block sums ----------------
__global__ void reduce_kernel(int nb) {
    __shared__ float s[512];
    int t = threadIdx.x;
    float a = 0.f;
    for (int i = t; i < nb; i += 512) a += g_bsum[i];
    s[t] = a;
    __syncthreads();
    for (int off = 256; off > 0; off >>= 1) {
        if (t < off) s[t] += s[t + off];
        __syncthreads();
    }
    if (t == 0) g_total = s[0];
}

// ---------------- kernel 6: normalize ops ----------------
__global__ void scale_kernel(float* __restrict__ out, int N) {
    int i = blockIdx.x * blockDim.x + threadIdx.x;
    float inv = 1.0f / g_total;
    if (i < N) out[i] *= inv;
}

// ---------------- kernel 7: prlvl branch ----------------
__global__ void prlvl_kernel(const float* __restrict__ prW1,
                             const float* __restrict__ prW2, const float* __restrict__ prb2,
                             const float* __restrict__ prW3, const float* __restrict__ prb3,
                             const float* __restrict__ msk,
                             float* __restrict__ out, int W, int out_off)
{
    int d = blockIdx.x, w = threadIdx.x;
    __shared__ float sW2[NH1 * NH2];
    __shared__ float sB2[NH2];
    __shared__ float sW3[NH2];
    __shared__ float sRow0[NH1];   // limit weights: W1 row 0
    __shared__ float sBase[NH1];   // ydag_pr[d] + zsum_pr
    __shared__ float red[64];

    for (int i = w; i < NH1 * NH2; i += 64) sW2[i] = prW2[i];
    if (w < NH2) { sB2[w] = prb2[w]; sW3[w] = prW3[w]; }
    if (w < NH1) {
        sRow0[w] = prW1[w];
        sBase[w] = g_ydag_pr[d * NH1 + w] + g_zsum_pr[w];
    }
    __syncthreads();

    float lim = (float)(w + 1);
    float h2[NH2];
    #pragma unroll
    for (int j = 0; j < NH2; j++) h2[j] = sB2[j];
    #pragma unroll
    for (int k = 0; k < NH1; k++) {
        float h = fmaxf(sBase[k] + lim * sRow0[k], 0.f);
        #pragma unroll
        for (int j = 0; j < NH2; j++) h2[j] += h * sW2[k * NH2 + j];
    }
    float o = prb3[0];
    #pragma unroll
    for (int j = 0; j < NH2; j++) o += fmaxf(h2[j], 0.f) * sW3[j];

    float logit = o - (1.0f - msk[d * W + w]) * 1000.0f;
    float e = expf(logit);
    red[w] = e;
    __syncthreads();
    for (int off = 32; off > 0; off >>= 1) {
        if (w < off) red[w] += red[w + off];
        __syncthreads();
    }
    out[out_off + d * W + w] = e / red[0];
}

// ---------------- launch ----------------
extern "C" void kernel_launch(void* const* d_in, const int* in_sizes, int n_in,
                              void* d_out, int out_size) {
    const int o = (n_in >= 20) ? 3 : 1;   // num_dags/num_workers scalars may be present

    const int*   num_ops = (const int*)d_in[0];
    const float* x       = (const float*)d_in[o + 0];
    const float* y       = (const float*)d_in[o + 1];
    const float* z       = (const float*)d_in[o + 2];
    const float* op_msk  = (const float*)d_in[o + 3];
    const float* pr_msk  = (const float*)d_in[o + 4];
    const float* opW1 = (const float*)d_in[o + 5];
    const float* opb1 = (const float*)d_in[o + 6];
    const float* opW2 = (const float*)d_in[o + 7];
    const float* opb2 = (const float*)d_in[o + 8];
    const float* opW3 = (const float*)d_in[o + 9];
    const float* opb3 = (const float*)d_in[o + 10];
    const float* prW1 = (const float*)d_in[o + 11];
    const float* prb1 = (const float*)d_in[o + 12];
    const float* prW2 = (const float*)d_in[o + 13];
    const float* prb2 = (const float*)d_in[o + 14];
    const float* prW3 = (const float*)d_in[o + 15];
    const float* prb3 = (const float*)d_in[o + 16];

    const int D = in_sizes[0];
    const int N = in_sizes[o + 3];
    const int W = in_sizes[o + 4] / D;
    float* out = (float*)d_out;

    scan_kernel<<<1, 1024>>>(num_ops, D);
    zsum_kernel<<<1, 64>>>(z, opW1, opb1, prW1, prb1);
    ydag_kernel<<<D, 64>>>(y, opW1, prW1);

    int nb = (N + OPK_T - 1) / OPK_T;
    op_main<<<nb, OPK_T>>>(x, opW1, opW2, opb2, opW3, opb3, op_msk, out, N, D);
    reduce_kernel<<<1, 512>>>(nb);
    scale_kernel<<<(N + 255) / 256, 256>>>(out, N);

    prlvl_kernel<<<D, 64>>>(prW1, prW2, prb2, prW3, prb3, pr_msk, out, W, N);

    (void)out_size; (void)n_in;
}